// round 8
// baseline (speedup 1.0000x reference)
#include <cuda_runtime.h>
#include <cuda_bf16.h>
#include <cstdint>

#define N_NODES 100000
#define N_EDGES 2000000
#define DIM 64
#define CAP 96   // max in-degree capacity (deg ~ Poisson(20); P(max>96) ~ 0)

#define AS_W 132                 // padded As row width (floats); 132%32=4 -> 2-way STS conflicts
#define NODES_PER_BLK 128

typedef unsigned long long ull;

// Scratch (no cudaMalloc allowed)
__device__ int g_cnt[N_NODES];
__device__ __align__(16) int g_adj[(size_t)N_NODES * CAP];          // 38.4 MB
__device__ __align__(16) float g_h1[(size_t)N_NODES * DIM];

// ---- f32x2 packed-FMA helpers (sm_103a) -----------------------------------
__device__ __forceinline__ ull rep2(float x) {
    ull r; asm("mov.b64 %0, {%1, %1};" : "=l"(r) : "f"(x)); return r;
}
__device__ __forceinline__ void fma2(ull& d, ull a, ull b) {
    asm("fma.rn.f32x2 %0, %1, %2, %0;" : "+l"(d) : "l"(a), "l"(b));
}
__device__ __forceinline__ float2 unpack2(ull v) {
    float2 f; asm("mov.b64 {%0, %1}, %2;" : "=f"(f.x), "=f"(f.y) : "l"(v)); return f;
}

// ---------------------------------------------------------------------------
// Build per-destination adjacency buckets: g_adj[dst*CAP + slot] = src.
// ---------------------------------------------------------------------------
__global__ void __launch_bounds__(256)
build_adj_kernel(const int* __restrict__ ei)
{
    unsigned e0 = (blockIdx.x * blockDim.x + threadIdx.x) * 4;
    if (e0 >= N_EDGES) return;
    int4 s4 = *reinterpret_cast<const int4*>(ei + e0);
    int4 d4 = *reinterpret_cast<const int4*>(ei + N_EDGES + e0);
    int ss[4] = {s4.x, s4.y, s4.z, s4.w};
    int dd[4] = {d4.x, d4.y, d4.z, d4.w};
    #pragma unroll
    for (int i = 0; i < 4; i++) {
        int slot = atomicAdd(&g_cnt[dd[i]], 1);
        if (slot < CAP) g_adj[(size_t)dd[i] * CAP + slot] = ss[i];
    }
}

// ---------------------------------------------------------------------------
// Fused layer: per block of 128 nodes,
//   Phase A: stage permuted W into Bs; gather neighbor means DIRECTLY into the
//            transposed As tile (k-rows permuted: feature 4c+i -> row 16i+c,
//            same permutation applied to W rows, so the GEMM sum is unchanged).
//   Phase B: register-tiled GEMM, 256 threads, 4 nodes x 8 cols each, f32x2.
// Two blocks co-reside per SM (100KB smem) so Phase B of one block overlaps
// Phase A (L2-bound) of the other.
// ---------------------------------------------------------------------------
template <bool RELU>
__global__ void __launch_bounds__(256)
fused_layer_kernel(const float* __restrict__ h,
                   const float* __restrict__ W,
                   const float* __restrict__ b,
                   float* __restrict__ out)
{
    extern __shared__ float smem[];
    float* As = smem;                       // [128 k][AS_W] (132-padded)
    float* Bs = smem + 128 * AS_W;          // [128 k][64 col] permuted rows
    __shared__ float bs[64];

    const int tid = threadIdx.x;
    const int base = blockIdx.x * NODES_PER_BLK;

    // ---- Stage W (k-rows permuted to match gather's transposed writes) ----
    {
        // row r (= blk*64 + 16i + c) <- W row (blk*64 + 4c + i); 2 threads/row
        int r = tid >> 1;
        int hr = tid & 1;
        int blk = (r & 64);
        int rr = r & 63;
        int i = rr >> 4;
        int c = rr & 15;
        int src = blk + 4 * c + i;
        const float4* W4 = reinterpret_cast<const float4*>(W);
        float4* Bs4w = reinterpret_cast<float4*>(Bs);
        #pragma unroll
        for (int q = 0; q < 8; q++)
            Bs4w[r * 16 + hr * 8 + q] = W4[src * 16 + hr * 8 + q];
        if (tid < 64) bs[tid] = b[tid];
    }

    // ---- Gather into As (warp per node stream; 16 nodes per warp) ----
    {
        const int lane = tid & 31;
        const int half = lane >> 4;
        const int sub  = lane & 15;
        const int warp = tid >> 5;
        const float4* __restrict__ h4 = reinterpret_cast<const float4*>(h);

        for (int nl = warp * 16; nl < warp * 16 + 16; nl++) {
            int node = base + nl;
            if (node >= N_NODES) break;

            const int deg = g_cnt[node];
            const int cnt = min(deg, CAP);
            const int* __restrict__ adj = g_adj + node * CAP;

            // self features: feature 4*sub+i -> As row 16i+sub
            if (half == 0) {
                float4 sv = h4[(size_t)node * 16 + sub];
                As[(sub)      * AS_W + nl] = sv.x;
                As[(16 + sub) * AS_W + nl] = sv.y;
                As[(32 + sub) * AS_W + nl] = sv.z;
                As[(48 + sub) * AS_W + nl] = sv.w;
            }

            float4 acc = make_float4(0.f, 0.f, 0.f, 0.f);
            int j = 0;
            for (; j + 8 <= cnt; j += 8) {
                int4 ia = *reinterpret_cast<const int4*>(adj + j);
                int4 ib = *reinterpret_cast<const int4*>(adj + j + 4);
                int s0 = half ? ia.y : ia.x;
                int s1 = half ? ia.w : ia.z;
                int s2 = half ? ib.y : ib.x;
                int s3 = half ? ib.w : ib.z;
                float4 v0 = h4[s0 * 16 + sub];
                float4 v1 = h4[s1 * 16 + sub];
                float4 v2 = h4[s2 * 16 + sub];
                float4 v3 = h4[s3 * 16 + sub];
                acc.x += (v0.x + v1.x) + (v2.x + v3.x);
                acc.y += (v0.y + v1.y) + (v2.y + v3.y);
                acc.z += (v0.z + v1.z) + (v2.z + v3.z);
                acc.w += (v0.w + v1.w) + (v2.w + v3.w);
            }
            for (; j + 2 <= cnt; j += 2) {
                int2 ia = *reinterpret_cast<const int2*>(adj + j);
                int s = half ? ia.y : ia.x;
                float4 v = h4[s * 16 + sub];
                acc.x += v.x; acc.y += v.y; acc.z += v.z; acc.w += v.w;
            }
            if (j < cnt && half == 0) {
                float4 v = h4[adj[j] * 16 + sub];
                acc.x += v.x; acc.y += v.y; acc.z += v.z; acc.w += v.w;
            }

            acc.x += __shfl_xor_sync(0xffffffffu, acc.x, 16);
            acc.y += __shfl_xor_sync(0xffffffffu, acc.y, 16);
            acc.z += __shfl_xor_sync(0xffffffffu, acc.z, 16);
            acc.w += __shfl_xor_sync(0xffffffffu, acc.w, 16);

            if (half == 0) {
                float inv = 1.0f / fmaxf((float)deg, 1.0f);
                // agg feature 4*sub+i -> As row 64 + 16i + sub
                As[(64 + sub)      * AS_W + nl] = acc.x * inv;
                As[(64 + 16 + sub) * AS_W + nl] = acc.y * inv;
                As[(64 + 32 + sub) * AS_W + nl] = acc.z * inv;
                As[(64 + 48 + sub) * AS_W + nl] = acc.w * inv;
            }
        }
    }
    __syncthreads();

    // ---- GEMM: 4 nodes x 8 cols per thread, f32x2 accumulators ----
    const int tx = tid & 31;    // node group (4 nodes)
    const int ty = tid >> 5;    // col group (8 cols), warp-uniform -> B broadcast

    const ulonglong2* __restrict__ Asu = reinterpret_cast<const ulonglong2*>(As);
    const float4* __restrict__ Bs4 = reinterpret_cast<const float4*>(Bs);

    ull acc2[2][8];
    #pragma unroll
    for (int i = 0; i < 2; i++)
        #pragma unroll
        for (int j = 0; j < 8; j++) acc2[i][j] = 0ull;

    #pragma unroll 8
    for (int k = 0; k < 128; k++) {
        ulonglong2 a = Asu[k * (AS_W / 4) + tx];    // nodes 4tx..4tx+3
        float4 b0 = Bs4[k * 16 + ty * 2];
        float4 b1 = Bs4[k * 16 + ty * 2 + 1];
        ull av0 = a.x, av1 = a.y;
        float bv[8] = {b0.x, b0.y, b0.z, b0.w, b1.x, b1.y, b1.z, b1.w};
        #pragma unroll
        for (int j = 0; j < 8; j++) {
            ull bj = rep2(bv[j]);
            fma2(acc2[0][j], av0, bj);
            fma2(acc2[1][j], av1, bj);
        }
    }

    // ---- Epilogue ----
    float4* out4 = reinterpret_cast<float4*>(out);
    #pragma unroll
    for (int p = 0; p < 2; p++) {
        float oe[8], oo[8];
        #pragma unroll
        for (int j = 0; j < 8; j++) {
            float2 v = unpack2(acc2[p][j]);
            float bb = bs[ty * 8 + j];
            float e = v.x + bb, o = v.y + bb;
            if (RELU) { e = fmaxf(e, 0.0f); o = fmaxf(o, 0.0f); }
            oe[j] = e; oo[j] = o;
        }
        int node_e = base + tx * 4 + 2 * p;
        if (node_e < N_NODES) {
            out4[(size_t)node_e * 16 + ty * 2]     = make_float4(oe[0], oe[1], oe[2], oe[3]);
            out4[(size_t)node_e * 16 + ty * 2 + 1] = make_float4(oe[4], oe[5], oe[6], oe[7]);
        }
        if (node_e + 1 < N_NODES) {
            out4[(size_t)(node_e + 1) * 16 + ty * 2]     = make_float4(oo[0], oo[1], oo[2], oo[3]);
            out4[(size_t)(node_e + 1) * 16 + ty * 2 + 1] = make_float4(oo[4], oo[5], oo[6], oo[7]);
        }
    }
}

extern "C" void kernel_launch(void* const* d_in, const int* in_sizes, int n_in,
                              void* d_out, int out_size)
{
    const float* x  = (const float*)d_in[0];
    const int*   ei = (const int*)  d_in[1];
    const float* W0 = (const float*)d_in[2];
    const float* b0 = (const float*)d_in[3];
    const float* W1 = (const float*)d_in[4];
    const float* b1 = (const float*)d_in[5];
    float* out = (float*)d_out;

    void *cnt_ptr = nullptr, *h1_ptr = nullptr;
    cudaGetSymbolAddress(&cnt_ptr, g_cnt);
    cudaGetSymbolAddress(&h1_ptr,  g_h1);
    float* h1 = (float*)h1_ptr;

    const int smem_bytes = (128 * AS_W + 128 * 64) * sizeof(float);  // 100352B
    cudaFuncSetAttribute(fused_layer_kernel<true>,
                         cudaFuncAttributeMaxDynamicSharedMemorySize, smem_bytes);
    cudaFuncSetAttribute(fused_layer_kernel<false>,
                         cudaFuncAttributeMaxDynamicSharedMemorySize, smem_bytes);

    const int build_blocks = (N_EDGES / 4 + 255) / 256;
    const int layer_blocks = (N_NODES + NODES_PER_BLK - 1) / NODES_PER_BLK;  // 782

    cudaMemsetAsync(cnt_ptr, 0, N_NODES * sizeof(int));
    build_adj_kernel<<<build_blocks, 256>>>(ei);

    fused_layer_kernel<true ><<<layer_blocks, 256, smem_bytes>>>(x,  W0, b0, h1);
    fused_layer_kernel<false><<<layer_blocks, 256, smem_bytes>>>(h1, W1, b1, out);
}